// round 11
// baseline (speedup 1.0000x reference)
#include <cuda_runtime.h>
#include <math.h>
#include <stdint.h>

// Problem constants (fixed by the reference)
#define NN 100000
#define EE 1600000
#define DD 128
#define CC 40
#define LNEPS 1e-5f
#define FULL 0xffffffffu

// ---------------- scratch (device globals; no runtime allocation) ----------------
__device__ int   g_is64;
__device__ int   g_cnt[NN];
__device__ int   g_tmp[NN];
__device__ int   g_bsum[256];
__device__ int   g_boff[256];
__device__ int   g_rowptr[NN + 1];
__device__ int   g_cursor[NN];
__device__ float g_dinv[NN];
__device__ float g_dinv2[NN];
__device__ int   g_src[EE];
__device__ float g_w[EE];
__device__ float g_h[(size_t)NN * DD];
__device__ float g_x0[(size_t)NN * DD];
__device__ float g_x1[(size_t)NN * DD];

// ---------------- dtype detection (int64 vs int32 edge_index) ----------------
__global__ void kdetect(const void* ei) {
    const unsigned int* w = (const unsigned int*)ei;
    int is64 = 1;
    for (int i = 0; i < 64; ++i) {
        if (w[2 * i + 1] != 0u) { is64 = 0; break; }
    }
    g_is64 = is64;
}

__device__ __forceinline__ int load_idx(const void* ei, long long pos) {
    if (g_is64) return (int)((const long long*)ei)[pos];
    return ((const int*)ei)[pos];
}

// ---------------- degree / CSR build ----------------
__global__ void kzero(int n) {
    int i = blockIdx.x * blockDim.x + threadIdx.x;
    if (i < n) g_cnt[i] = 0;
}

__global__ void khist(const void* ei, int ne) {
    int e = blockIdx.x * blockDim.x + threadIdx.x;
    if (e >= ne) return;
    int d = load_idx(ei, (long long)ne + e);
    atomicAdd(&g_cnt[d], 1);
}

__global__ void kdinv(int n) {
    int i = blockIdx.x * blockDim.x + threadIdx.x;
    if (i >= n) return;
    float deg = (float)g_cnt[i] + 1.0f;   // +1: self-loop
    float di = rsqrtf(deg);
    g_dinv[i] = di;
    g_dinv2[i] = di * di;
}

// exclusive scan of g_cnt -> g_rowptr (3 passes, 1024 items/block)
__global__ void kscan1(int n) {
    __shared__ int sh[256];
    int b = blockIdx.x, tid = threadIdx.x;
    int base = b * 1024 + tid * 4;
    int v0 = (base + 0 < n) ? g_cnt[base + 0] : 0;
    int v1 = (base + 1 < n) ? g_cnt[base + 1] : 0;
    int v2 = (base + 2 < n) ? g_cnt[base + 2] : 0;
    int v3 = (base + 3 < n) ? g_cnt[base + 3] : 0;
    int t1 = v0 + v1, t2 = t1 + v2, t3 = t2 + v3;
    sh[tid] = t3;
    __syncthreads();
    for (int off = 1; off < 256; off <<= 1) {
        int add = (tid >= off) ? sh[tid - off] : 0;
        __syncthreads();
        sh[tid] += add;
        __syncthreads();
    }
    int excl = sh[tid] - t3;
    if (base + 0 < n) g_tmp[base + 0] = excl;
    if (base + 1 < n) g_tmp[base + 1] = excl + v0;
    if (base + 2 < n) g_tmp[base + 2] = excl + t1;
    if (base + 3 < n) g_tmp[base + 3] = excl + t2;
    if (tid == 255) g_bsum[b] = sh[255];
}

__global__ void kscan2(int nb) {
    __shared__ int sh[256];
    int tid = threadIdx.x;
    int v = (tid < nb) ? g_bsum[tid] : 0;
    sh[tid] = v;
    __syncthreads();
    for (int off = 1; off < 256; off <<= 1) {
        int add = (tid >= off) ? sh[tid - off] : 0;
        __syncthreads();
        sh[tid] += add;
        __syncthreads();
    }
    if (tid < nb) g_boff[tid] = sh[tid] - v;
}

__global__ void kscan3(int n, int etot) {
    int i = blockIdx.x * blockDim.x + threadIdx.x;
    if (i < n) {
        int r = g_tmp[i] + g_boff[i >> 10];
        g_rowptr[i] = r;
        g_cursor[i] = r;
    }
    if (i == 0) g_rowptr[n] = etot;
}

__global__ void kscatter(const void* ei, int ne) {
    int e = blockIdx.x * blockDim.x + threadIdx.x;
    if (e >= ne) return;
    int s = load_idx(ei, e);
    int d = load_idx(ei, (long long)ne + e);
    int pos = atomicAdd(&g_cursor[d], 1);
    g_src[pos] = s;
    g_w[pos] = g_dinv[s] * g_dinv[d];
}

// ---------------- SGEMM: h = X @ W  (X [N,128], W [128,128]) ----------------
// BM=128, BN=128, BK=32, 256 threads, 8x8 micro-tile per thread.
__global__ __launch_bounds__(256) void gemm128(const float* __restrict__ Xext,
                                               int xsel,
                                               const float* __restrict__ Wg,
                                               int nrows) {
    const float* __restrict__ X = (xsel == 0) ? Xext : (xsel == 1 ? g_x0 : g_x1);

    __shared__ float Xs[128][36];   // [m][k], padded row
    __shared__ float Ws[32][128];   // [k][n]

    int tx = threadIdx.x;           // 0..15 (cols)
    int ty = threadIdx.y;           // 0..15 (rows)
    int tid = ty * 16 + tx;
    int m0 = blockIdx.x * 128;

    float acc[8][8];
#pragma unroll
    for (int i = 0; i < 8; ++i)
#pragma unroll
        for (int j = 0; j < 8; ++j) acc[i][j] = 0.0f;

    for (int kt = 0; kt < 128; kt += 32) {
#pragma unroll
        for (int it = 0; it < 4; ++it) {
            int f4 = tid + it * 256;
            {   // X tile
                int m = f4 >> 3, kq = f4 & 7;
                float4 v = make_float4(0.f, 0.f, 0.f, 0.f);
                int gm = m0 + m;
                if (gm < nrows) v = *(const float4*)&X[(size_t)gm * DD + kt + kq * 4];
                *(float4*)&Xs[m][kq * 4] = v;
            }
            {   // W tile
                int k = f4 >> 5, nq = f4 & 31;
                *(float4*)&Ws[k][nq * 4] = *(const float4*)&Wg[(size_t)(kt + k) * DD + nq * 4];
            }
        }
        __syncthreads();

#pragma unroll 8
        for (int k = 0; k < 32; ++k) {
            float4 w0 = *(const float4*)&Ws[k][tx * 4];
            float4 w1 = *(const float4*)&Ws[k][64 + tx * 4];
#pragma unroll
            for (int i = 0; i < 8; ++i) {
                float xv = Xs[ty * 8 + i][k];
                acc[i][0] += xv * w0.x; acc[i][1] += xv * w0.y;
                acc[i][2] += xv * w0.z; acc[i][3] += xv * w0.w;
                acc[i][4] += xv * w1.x; acc[i][5] += xv * w1.y;
                acc[i][6] += xv * w1.z; acc[i][7] += xv * w1.w;
            }
        }
        __syncthreads();
    }

#pragma unroll
    for (int i = 0; i < 8; ++i) {
        int m = m0 + ty * 8 + i;
        if (m < nrows) {
            float4 o0 = make_float4(acc[i][0], acc[i][1], acc[i][2], acc[i][3]);
            float4 o1 = make_float4(acc[i][4], acc[i][5], acc[i][6], acc[i][7]);
            *(float4*)&g_h[(size_t)m * DD + tx * 4] = o0;
            *(float4*)&g_h[(size_t)m * DD + 64 + tx * 4] = o1;
        }
    }
}

// ---------------- fused aggregation + LayerNorm + ELU + residual ----------------
// one warp per node; lane owns features [lane*4, lane*4+4)
__global__ __launch_bounds__(256) void agg_ln(const float* __restrict__ bias,
                                              const float* __restrict__ gamma,
                                              const float* __restrict__ beta,
                                              const float* __restrict__ resid_ext,
                                              int rsel, int osel, int has_resid) {
    int gw = (blockIdx.x * blockDim.x + threadIdx.x) >> 5;
    int lane = threadIdx.x & 31;
    if (gw >= NN) return;
    int f = lane * 4;

    float d2 = g_dinv2[gw];
    float4 hv = *(const float4*)&g_h[(size_t)gw * DD + f];
    float4 bv = *(const float4*)&bias[f];
    float a0 = hv.x * d2 + bv.x;
    float a1 = hv.y * d2 + bv.y;
    float a2 = hv.z * d2 + bv.z;
    float a3 = hv.w * d2 + bv.w;

    int beg = g_rowptr[gw], end = g_rowptr[gw + 1];
    for (int j0 = beg; j0 < end; j0 += 32) {
        int jj = j0 + lane;
        int s = 0; float w = 0.0f;
        if (jj < end) { s = g_src[jj]; w = g_w[jj]; }
        int cnt = min(32, end - j0);
        int t = 0;
        for (; t + 4 <= cnt; t += 4) {
            int s0 = __shfl_sync(FULL, s, t + 0);
            int s1 = __shfl_sync(FULL, s, t + 1);
            int s2 = __shfl_sync(FULL, s, t + 2);
            int s3 = __shfl_sync(FULL, s, t + 3);
            float w0 = __shfl_sync(FULL, w, t + 0);
            float w1 = __shfl_sync(FULL, w, t + 1);
            float w2 = __shfl_sync(FULL, w, t + 2);
            float w3 = __shfl_sync(FULL, w, t + 3);
            float4 v0 = *(const float4*)&g_h[(size_t)s0 * DD + f];
            float4 v1 = *(const float4*)&g_h[(size_t)s1 * DD + f];
            float4 v2 = *(const float4*)&g_h[(size_t)s2 * DD + f];
            float4 v3 = *(const float4*)&g_h[(size_t)s3 * DD + f];
            a0 += v0.x * w0 + v1.x * w1 + v2.x * w2 + v3.x * w3;
            a1 += v0.y * w0 + v1.y * w1 + v2.y * w2 + v3.y * w3;
            a2 += v0.z * w0 + v1.z * w1 + v2.z * w2 + v3.z * w3;
            a3 += v0.w * w0 + v1.w * w1 + v2.w * w2 + v3.w * w3;
        }
        for (; t < cnt; ++t) {
            int ss = __shfl_sync(FULL, s, t);
            float ww = __shfl_sync(FULL, w, t);
            float4 v = *(const float4*)&g_h[(size_t)ss * DD + f];
            a0 += v.x * ww; a1 += v.y * ww; a2 += v.z * ww; a3 += v.w * ww;
        }
    }

    // LayerNorm (biased variance)
    float s1 = a0 + a1 + a2 + a3;
    float s2 = a0 * a0 + a1 * a1 + a2 * a2 + a3 * a3;
#pragma unroll
    for (int off = 16; off > 0; off >>= 1) {
        s1 += __shfl_xor_sync(FULL, s1, off);
        s2 += __shfl_xor_sync(FULL, s2, off);
    }
    float mean = s1 * (1.0f / 128.0f);
    float var = s2 * (1.0f / 128.0f) - mean * mean;
    float rstd = rsqrtf(var + LNEPS);

    float4 gv = *(const float4*)&gamma[f];
    float4 bev = *(const float4*)&beta[f];
    float y0 = (a0 - mean) * rstd * gv.x + bev.x;
    float y1 = (a1 - mean) * rstd * gv.y + bev.y;
    float y2 = (a2 - mean) * rstd * gv.z + bev.z;
    float y3 = (a3 - mean) * rstd * gv.w + bev.w;

    // ELU (alpha = 1)
    y0 = (y0 > 0.f) ? y0 : expm1f(y0);
    y1 = (y1 > 0.f) ? y1 : expm1f(y1);
    y2 = (y2 > 0.f) ? y2 : expm1f(y2);
    y3 = (y3 > 0.f) ? y3 : expm1f(y3);

    if (has_resid) {
        const float* __restrict__ R = (rsel == 1) ? g_x0 : (rsel == 2 ? g_x1 : resid_ext);
        float4 rv = *(const float4*)&R[(size_t)gw * DD + f];
        y0 += rv.x; y1 += rv.y; y2 += rv.z; y3 += rv.w;
    }

    float* __restrict__ O = (osel == 1) ? g_x0 : g_x1;
    *(float4*)&O[(size_t)gw * DD + f] = make_float4(y0, y1, y2, y3);
}

// ---------------- classifier: out = x @ Wc + bc  (x = g_x0) ----------------
// blockDim (40, 8) = 320 threads; 128 rows per block; thread = 1 col x 16 rows.
__global__ __launch_bounds__(320) void classifier(const float* __restrict__ Wc,
                                                  const float* __restrict__ bc,
                                                  float* __restrict__ Out) {
    __shared__ float Wcs[DD * CC];     // [k][c]
    __shared__ float XsT[32][132];     // [k][m] transposed, padded to keep f4 alignment

    int col = threadIdx.x;             // 0..39
    int ty = threadIdx.y;              // 0..7
    int tid = ty * 40 + col;
    int m0 = blockIdx.x * 128;

    for (int i = tid; i < DD * CC; i += 320) Wcs[i] = Wc[i];

    float acc[16];
    float bcv = bc[col];
#pragma unroll
    for (int r = 0; r < 16; ++r) acc[r] = bcv;

    for (int kt = 0; kt < DD; kt += 32) {
        for (int f4 = tid; f4 < 1024; f4 += 320) {
            int m = f4 >> 3, kq = f4 & 7;
            float4 v = make_float4(0.f, 0.f, 0.f, 0.f);
            int gm = m0 + m;
            if (gm < NN) v = *(const float4*)&g_x0[(size_t)gm * DD + kt + kq * 4];
            XsT[kq * 4 + 0][m] = v.x;
            XsT[kq * 4 + 1][m] = v.y;
            XsT[kq * 4 + 2][m] = v.z;
            XsT[kq * 4 + 3][m] = v.w;
        }
        __syncthreads();
#pragma unroll 8
        for (int k = 0; k < 32; ++k) {
            float w = Wcs[(kt + k) * CC + col];
#pragma unroll
            for (int r4 = 0; r4 < 4; ++r4) {
                float4 xv = *(const float4*)&XsT[k][ty * 16 + r4 * 4];
                acc[r4 * 4 + 0] += xv.x * w;
                acc[r4 * 4 + 1] += xv.y * w;
                acc[r4 * 4 + 2] += xv.z * w;
                acc[r4 * 4 + 3] += xv.w * w;
            }
        }
        __syncthreads();
    }

#pragma unroll
    for (int r = 0; r < 16; ++r) {
        int m = m0 + ty * 16 + r;
        if (m < NN) Out[(size_t)m * CC + col] = acc[r];
    }
}

// ---------------- launch ----------------
extern "C" void kernel_launch(void* const* d_in, const int* in_sizes, int n_in,
                              void* d_out, int out_size) {
    const float* x = (const float*)d_in[0];
    const void* ei = d_in[1];
    const float* W[3]  = {(const float*)d_in[2],  (const float*)d_in[6],  (const float*)d_in[10]};
    const float* b[3]  = {(const float*)d_in[3],  (const float*)d_in[7],  (const float*)d_in[11]};
    const float* ga[3] = {(const float*)d_in[4],  (const float*)d_in[8],  (const float*)d_in[12]};
    const float* be[3] = {(const float*)d_in[5],  (const float*)d_in[9],  (const float*)d_in[13]};
    const float* Wc = (const float*)d_in[14];
    const float* bc = (const float*)d_in[15];
    float* out = (float*)d_out;

    int ne = in_sizes[1] / 2;

    // graph preprocessing: degrees, dinv, CSR by dst
    kdetect<<<1, 1>>>(ei);
    kzero<<<(NN + 255) / 256, 256>>>(NN);
    khist<<<(ne + 255) / 256, 256>>>(ei, ne);
    kdinv<<<(NN + 255) / 256, 256>>>(NN);
    int nb = (NN + 1023) / 1024;
    kscan1<<<nb, 256>>>(NN);
    kscan2<<<1, 256>>>(nb);
    kscan3<<<(NN + 255) / 256, 256>>>(NN, ne);
    kscatter<<<(ne + 255) / 256, 256>>>(ei, ne);

    dim3 gthreads(16, 16);
    int gblocks = (NN + 127) / 128;
    int ablocks = (NN * 32 + 255) / 256;

    // layer 0: x(ext) -> h -> x0   (no residual)
    gemm128<<<gblocks, gthreads>>>(x, 0, W[0], NN);
    agg_ln<<<ablocks, 256>>>(b[0], ga[0], be[0], nullptr, 0, 1, 0);
    // layer 1: x0 -> h -> x1 (+x0 residual)
    gemm128<<<gblocks, gthreads>>>(nullptr, 1, W[1], NN);
    agg_ln<<<ablocks, 256>>>(b[1], ga[1], be[1], nullptr, 1, 2, 1);
    // layer 2: x1 -> h -> x0 (+x1 residual)
    gemm128<<<gblocks, gthreads>>>(nullptr, 2, W[2], NN);
    agg_ln<<<ablocks, 256>>>(b[2], ga[2], be[2], nullptr, 2, 1, 1);

    // classifier reads g_x0
    classifier<<<(NN + 127) / 128, dim3(40, 8)>>>(Wc, bc, out);
    (void)n_in; (void)out_size;
}